// round 10
// baseline (speedup 1.0000x reference)
#include <cuda_runtime.h>
#include <cstdint>

// Problem constants (fixed by the dataset)
constexpr int D      = 128;     // embed size
constexpr int H      = 256;     // hidden size
constexpr int NODES  = 8192;    // 2*B
constexpr int BP     = 4096;    // pairs
constexpr int T_EDG  = NODES * 32;
constexpr int K1     = 3 * D;   // 384
constexpr int K2     = 2 * H;   // 512

constexpr int NCHUNK      = 8;
constexpr int CHUNK_NODES = NODES / NCHUNK;   // 1024

// Scratch
__device__ float g_A1[(size_t)NODES * K1];
__device__ float g_W1p[K1 * H];   // W1 packed in mma-fragment order
__device__ float g_Wrp[K2 * H];   // Wr packed in mma-fragment order
__device__ float g_b1[H];

__device__ __forceinline__ uint32_t f2tf32(float f) {
    uint32_t u;
    asm("cvt.rna.tf32.f32 %0, %1;" : "=r"(u) : "f"(f));
    return u;
}
__device__ __forceinline__ float cvt_tf32(float f) {
    return __uint_as_float(f2tf32(f));
}

// ---------------------------------------------------------------------------
// Kernel 0: pack weights into mma-fragment order + fuse bias.
//   dst = ((t*2 + ks)*32 + j)*64 + lane*2 + r
//   src = W[k][col], k = t*16 + ks*8 + (lane&3) + r*4, col = j*8 + (lane>>2)
// ---------------------------------------------------------------------------
__global__ void prep_w(const float* __restrict__ Wt, const float* __restrict__ Wn,
                       const float* __restrict__ Wr,
                       const float* __restrict__ bt, const float* __restrict__ bn) {
    const int gt = blockIdx.x * blockDim.x + threadIdx.x;
    const int w1_sz = K1 * H;         // 98304
    const int wr_sz = K2 * H;         // 131072
    if (gt < w1_sz) {
        const int r    = gt & 1;
        const int lane = (gt >> 1) & 31;
        const int j    = (gt >> 6) & 31;
        const int ks   = (gt >> 11) & 1;
        const int t    = gt >> 12;
        const int k    = t * 16 + ks * 8 + (lane & 3) + r * 4;
        const int col  = j * 8 + (lane >> 2);
        const float v  = (k < D) ? Wt[k * H + col] : Wn[(k - D) * H + col];
        g_W1p[gt] = cvt_tf32(v);
    } else if (gt < w1_sz + wr_sz) {
        const int idx  = gt - w1_sz;
        const int r    = idx & 1;
        const int lane = (idx >> 1) & 31;
        const int j    = (idx >> 6) & 31;
        const int ks   = (idx >> 11) & 1;
        const int t    = idx >> 12;
        const int k    = t * 16 + ks * 8 + (lane & 3) + r * 4;
        const int col  = j * 8 + (lane >> 2);
        g_Wrp[idx] = cvt_tf32(Wr[k * H + col]);
    }
    if (gt < H) g_b1[gt] = bt[gt] + bn[gt];
}

// ---------------------------------------------------------------------------
// Kernel 1 (chunked): gather + segment mean, TWO warps per node.
// ---------------------------------------------------------------------------
__global__ void gather_mean(const float* __restrict__ E, const float* __restrict__ R,
                            const int* __restrict__ ents,
                            const int* __restrict__ nent,
                            const int* __restrict__ nrel,
                            const int* __restrict__ offs,
                            int node_base) {
    const int gw   = (blockIdx.x * blockDim.x + threadIdx.x) >> 5;
    const int lane = threadIdx.x & 31;
    const int node = node_base + (gw >> 1);
    const bool isE = (gw & 1) == 0;
    if (node >= NODES) return;

    const int start = offs[node];
    const int end   = (node + 1 < NODES) ? offs[node + 1] : T_EDG;
    const int cnt   = end - start;
    const float inv = 1.0f / (float)(cnt > 0 ? cnt : 1);

    float* row = g_A1 + (size_t)node * K1;

    if (isE) {
        const float4* E4 = (const float4*)E;
        float4 s = make_float4(0.f, 0.f, 0.f, 0.f);
        if (cnt == 32) {
            const int idx = nent[start + lane];
            #pragma unroll 8
            for (int j = 0; j < 32; j++) {
                const int ie = __shfl_sync(0xffffffffu, idx, j);
                float4 v = __ldg(&E4[(size_t)ie * (D / 4) + lane]);
                s.x += v.x; s.y += v.y; s.z += v.z; s.w += v.w;
            }
        } else {
            for (int base = start; base < end; base += 32) {
                const int rem = end - base;
                const int n   = rem < 32 ? rem : 32;
                const int idx = (lane < rem) ? nent[base + lane] : 0;
                #pragma unroll 4
                for (int j = 0; j < n; j++) {
                    const int ie = __shfl_sync(0xffffffffu, idx, j);
                    float4 v = __ldg(&E4[(size_t)ie * (D / 4) + lane]);
                    s.x += v.x; s.y += v.y; s.z += v.z; s.w += v.w;
                }
            }
        }
        float4 e = __ldg(&E4[(size_t)ents[node] * (D / 4) + lane]);
        float4 o0, o1;
        o0.x = cvt_tf32(e.x);       o0.y = cvt_tf32(e.y);
        o0.z = cvt_tf32(e.z);       o0.w = cvt_tf32(e.w);
        o1.x = cvt_tf32(s.x * inv); o1.y = cvt_tf32(s.y * inv);
        o1.z = cvt_tf32(s.z * inv); o1.w = cvt_tf32(s.w * inv);
        *(float4*)(row + lane * 4)     = o0;
        *(float4*)(row + D + lane * 4) = o1;
    } else {
        const float4* R4 = (const float4*)R;
        float4 s = make_float4(0.f, 0.f, 0.f, 0.f);
        if (cnt == 32) {
            const int idx = nrel[start + lane];
            #pragma unroll 8
            for (int j = 0; j < 32; j++) {
                const int ir = __shfl_sync(0xffffffffu, idx, j);
                float4 v = __ldg(&R4[(size_t)ir * (D / 4) + lane]);
                s.x += v.x; s.y += v.y; s.z += v.z; s.w += v.w;
            }
        } else {
            for (int base = start; base < end; base += 32) {
                const int rem = end - base;
                const int n   = rem < 32 ? rem : 32;
                const int idx = (lane < rem) ? nrel[base + lane] : 0;
                #pragma unroll 4
                for (int j = 0; j < n; j++) {
                    const int ir = __shfl_sync(0xffffffffu, idx, j);
                    float4 v = __ldg(&R4[(size_t)ir * (D / 4) + lane]);
                    s.x += v.x; s.y += v.y; s.z += v.z; s.w += v.w;
                }
            }
        }
        float4 o2;
        o2.x = cvt_tf32(s.x * inv); o2.y = cvt_tf32(s.y * inv);
        o2.z = cvt_tf32(s.z * inv); o2.w = cvt_tf32(s.w * inv);
        *(float4*)(row + 2 * D + lane * 4) = o2;
    }
}

// ---------------------------------------------------------------------------
__device__ __forceinline__ void cp16(void* smem, const void* gmem) {
    uint32_t s = (uint32_t)__cvta_generic_to_shared(smem);
    asm volatile("cp.async.cg.shared.global [%0], [%1], 16;" :: "r"(s), "l"(gmem));
}
__device__ __forceinline__ void mma_tf32(float* a4, uint32_t a0, uint32_t a1,
                                         uint32_t a2, uint32_t a3,
                                         uint32_t b0, uint32_t b1) {
    asm volatile(
        "mma.sync.aligned.m16n8k8.row.col.f32.tf32.tf32.f32 "
        "{%0,%1,%2,%3}, {%4,%5,%6,%7}, {%8,%9}, {%0,%1,%2,%3};"
        : "+f"(a4[0]), "+f"(a4[1]), "+f"(a4[2]), "+f"(a4[3])
        : "r"(a0), "r"(a1), "r"(a2), "r"(a3), "r"(b0), "r"(b1));
}

// ---------------------------------------------------------------------------
// Fused MLP (chunked): one CTA per 32 node-rows (= 16 pairs), 256 threads.
// ---------------------------------------------------------------------------
constexpr int BK     = 16;
constexpr int STAGES = 4;
constexpr int BM     = 32;
constexpr int BN     = 256;
constexpr int SAS    = BK + 4;             // 20
constexpr int SN     = 258;                // node-tile stride (conflict-free)
constexpr int A_SZ   = BM * SAS;           // 640
constexpr int B_SZ   = BK * BN;            // 4096 (packed, linear)
constexpr int FUSED_SMEM =
    (BM * SN + STAGES * A_SZ + STAGES * B_SZ) * 4;   // 108800 B

__global__ void __launch_bounds__(256, 2)
fused_mlp(const float* __restrict__ A1full, const float* __restrict__ W1p,
          const float* __restrict__ b1g, const float* __restrict__ Wrp,
          const float* __restrict__ br, float* __restrict__ out,
          int by_base) {
    constexpr int THREADS = 256;

    extern __shared__ float smem[];
    float* sN  = smem;                      // [32][SN]
    float* sAb = smem + BM * SN;            // STAGES * A_SZ
    float* sBb = sAb + STAGES * A_SZ;       // STAGES * B_SZ

    const int tid  = threadIdx.x;
    const int wid  = tid >> 5;
    const int lane = tid & 31;
    const int grp  = lane >> 2;
    const int tg   = lane & 3;
    const int by   = by_base + blockIdx.x;

    const float* Ag = A1full + (size_t)by * BM * K1;

    auto issueA = [&](int t, int stg) {
        if (tid < 128) {
            float* sA = sAb + stg * A_SZ;
            int row = tid >> 2;
            int c4  = tid & 3;
            cp16(&sA[row * SAS + c4 * 4],
                 Ag + (size_t)row * K1 + t * BK + c4 * 4);
        }
    };
    auto issueB = [&](const float* Wsrc, int t, int stg) {
        float* sB = sBb + stg * B_SZ;
        const float* src = Wsrc + (size_t)t * B_SZ;
        #pragma unroll
        for (int l = 0; l < 4; l++) {
            int o = (tid + l * THREADS) * 4;
            cp16(&sB[o], src + o);
        }
    };

    // =========================== PHASE 1 ===================================
    {
        const int wm = wid & 1;
        const int wn = wid >> 1;

        float acc[8][4];
        #pragma unroll
        for (int j = 0; j < 8; j++)
            #pragma unroll
            for (int c = 0; c < 4; c++) acc[j][c] = 0.f;

        const int nt1 = K1 / BK;   // 24
        #pragma unroll
        for (int s = 0; s < STAGES - 1; s++) {
            issueA(s, s); issueB(W1p, s, s);
            asm volatile("cp.async.commit_group;");
        }

        const int rb = wm * 16 + grp;
        for (int t = 0; t < nt1; t++) {
            asm volatile("cp.async.wait_group %0;" :: "n"(STAGES - 2));
            __syncthreads();
            const int nt = t + STAGES - 1;
            if (nt < nt1) { issueA(nt, nt % STAGES); issueB(W1p, nt, nt % STAGES); }
            asm volatile("cp.async.commit_group;");

            const float* sA = sAb + (t % STAGES) * A_SZ;
            const float* sB = sBb + (t % STAGES) * B_SZ;
            #pragma unroll
            for (int ks = 0; ks < 2; ks++) {
                uint32_t a0 = __float_as_uint(sA[(rb + 0) * SAS + ks * 8 + tg]);
                uint32_t a1 = __float_as_uint(sA[(rb + 8) * SAS + ks * 8 + tg]);
                uint32_t a2 = __float_as_uint(sA[(rb + 0) * SAS + ks * 8 + tg + 4]);
                uint32_t a3 = __float_as_uint(sA[(rb + 8) * SAS + ks * 8 + tg + 4]);
                #pragma unroll
                for (int jl = 0; jl < 8; jl++) {
                    const int j = wn * 8 + jl;
                    float2 b = *(const float2*)(&sB[((ks * 32 + j) << 6) + lane * 2]);
                    mma_tf32(acc[jl], a0, a1, a2, a3,
                             __float_as_uint(b.x), __float_as_uint(b.y));
                }
            }
        }

        asm volatile("cp.async.wait_group 0;");

        #pragma unroll
        for (int jl = 0; jl < 8; jl++) {
            const int c = wn * 64 + jl * 8 + tg * 2;
            const float b0 = b1g[c], b1v = b1g[c + 1];
            float2 v0, v1;
            v0.x = cvt_tf32(fmaxf(acc[jl][0] + b0, 0.f));
            v0.y = cvt_tf32(fmaxf(acc[jl][1] + b1v, 0.f));
            v1.x = cvt_tf32(fmaxf(acc[jl][2] + b0, 0.f));
            v1.y = cvt_tf32(fmaxf(acc[jl][3] + b1v, 0.f));
            *(float2*)(&sN[(rb + 0) * SN + c]) = v0;
            *(float2*)(&sN[(rb + 8) * SN + c]) = v1;
        }
        __syncthreads();
    }

    // =========================== PHASE 2 ===================================
    {
        const int wn2 = wid;

        float acc[4][4];
        #pragma unroll
        for (int j = 0; j < 4; j++)
            #pragma unroll
            for (int c = 0; c < 4; c++) acc[j][c] = 0.f;

        const int nt2 = K2 / BK;   // 32
        #pragma unroll
        for (int s = 0; s < STAGES - 1; s++) {
            issueB(Wrp, s, s);
            asm volatile("cp.async.commit_group;");
        }

        for (int t = 0; t < nt2; t++) {
            asm volatile("cp.async.wait_group %0;" :: "n"(STAGES - 2));
            __syncthreads();
            const int nt = t + STAGES - 1;
            if (nt < nt2) issueB(Wrp, nt, nt % STAGES);
            asm volatile("cp.async.commit_group;");

            const float* sB = sBb + (t % STAGES) * B_SZ;
            #pragma unroll
            for (int ks = 0; ks < 2; ks++) {
                const int k  = t * BK + ks * 8;
                const int h  = (k >= 256) ? 1 : 0;
                const int kk = k & 255;
                uint32_t a0 = __float_as_uint(sN[(2 * (grp + 0) + h) * SN + kk + tg]);
                uint32_t a1 = __float_as_uint(sN[(2 * (grp + 8) + h) * SN + kk + tg]);
                uint32_t a2 = __float_as_uint(sN[(2 * (grp + 0) + h) * SN + kk + tg + 4]);
                uint32_t a3 = __float_as_uint(sN[(2 * (grp + 8) + h) * SN + kk + tg + 4]);
                #pragma unroll
                for (int jl = 0; jl < 4; jl++) {
                    const int j = wn2 * 4 + jl;
                    float2 b = *(const float2*)(&sB[((ks * 32 + j) << 6) + lane * 2]);
                    mma_tf32(acc[jl], a0, a1, a2, a3,
                             __float_as_uint(b.x), __float_as_uint(b.y));
                }
            }
        }

        const int prow = by * 16 + grp;
        #pragma unroll
        for (int jl = 0; jl < 4; jl++) {
            const int c = wn2 * 32 + jl * 8 + tg * 2;
            const float b0 = br[c], b1v = br[c + 1];
            float2 v0, v1;
            v0.x = fmaxf(acc[jl][0] + b0, 0.f);
            v0.y = fmaxf(acc[jl][1] + b1v, 0.f);
            v1.x = fmaxf(acc[jl][2] + b0, 0.f);
            v1.y = fmaxf(acc[jl][3] + b1v, 0.f);
            *(float2*)(out + (size_t)(prow + 0) * H + c) = v0;
            *(float2*)(out + (size_t)(prow + 8) * H + c) = v1;
        }
    }
}

// ---------------------------------------------------------------------------
extern "C" void kernel_launch(void* const* d_in, const int* in_sizes, int n_in,
                              void* d_out, int out_size) {
    const float* E    = (const float*)d_in[0];
    const float* R    = (const float*)d_in[1];
    const float* Wt   = (const float*)d_in[2];
    const float* bt   = (const float*)d_in[3];
    const float* Wn   = (const float*)d_in[4];
    const float* bn   = (const float*)d_in[5];
    const float* Wr   = (const float*)d_in[6];
    const float* br   = (const float*)d_in[7];
    const int*   ents = (const int*)d_in[8];
    const int*   nent = (const int*)d_in[9];
    const int*   nrel = (const int*)d_in[10];
    const int*   offs = (const int*)d_in[11];
    float* out = (float*)d_out;

    float *A1, *W1p, *Wrp, *b1;
    cudaGetSymbolAddress((void**)&A1,  g_A1);
    cudaGetSymbolAddress((void**)&W1p, g_W1p);
    cudaGetSymbolAddress((void**)&Wrp, g_Wrp);
    cudaGetSymbolAddress((void**)&b1,  g_b1);

    // One-time host-side resources (streams/events; no device memory).
    static cudaStream_t s_mlp = nullptr;
    static cudaEvent_t  evG[NCHUNK];
    static cudaEvent_t  evDone = nullptr;
    if (s_mlp == nullptr) {
        cudaStreamCreateWithFlags(&s_mlp, cudaStreamNonBlocking);
        for (int c = 0; c < NCHUNK; c++)
            cudaEventCreateWithFlags(&evG[c], cudaEventDisableTiming);
        cudaEventCreateWithFlags(&evDone, cudaEventDisableTiming);
        cudaFuncSetAttribute(fused_mlp,
                             cudaFuncAttributeMaxDynamicSharedMemorySize,
                             FUSED_SMEM);
    }

    // 0) weight pack + bias fuse on main stream
    prep_w<<<((K1 + K2) * H + 255) / 256, 256>>>(Wt, Wn, Wr, bt, bn);

    // 1) chunked gathers on main stream, each followed by an event
    for (int c = 0; c < NCHUNK; c++) {
        gather_mean<<<CHUNK_NODES / 4, 256>>>(E, R, ents, nent, nrel, offs,
                                              c * CHUNK_NODES);
        cudaEventRecord(evG[c], 0);
    }

    // 2) chunked MLPs on the side stream, each gated on its gather chunk
    for (int c = 0; c < NCHUNK; c++) {
        cudaStreamWaitEvent(s_mlp, evG[c], 0);
        fused_mlp<<<CHUNK_NODES / BM, 256, FUSED_SMEM, s_mlp>>>(
            A1, W1p, b1, Wrp, br, out, c * (CHUNK_NODES / BM));
    }

    // 3) join side stream back into main stream
    cudaEventRecord(evDone, s_mlp);
    cudaStreamWaitEvent(0, evDone, 0);
}

// round 11
// speedup vs baseline: 2.7288x; 2.7288x over previous
#include <cuda_runtime.h>
#include <cstdint>

// Problem constants (fixed by the dataset)
constexpr int D      = 128;     // embed size
constexpr int H      = 256;     // hidden size
constexpr int NODES  = 8192;    // 2*B
constexpr int BP     = 4096;    // pairs
constexpr int T_EDG  = NODES * 32;
constexpr int K1     = 3 * D;   // 384
constexpr int K2     = 2 * H;   // 512

// Scratch
__device__ float g_A1[(size_t)NODES * K1];
__device__ float g_W1p[K1 * H];   // W1 packed in mma-fragment order
__device__ float g_Wrp[K2 * H];   // Wr packed in mma-fragment order
__device__ float g_b1[H];

__device__ __forceinline__ uint32_t f2tf32(float f) {
    uint32_t u;
    asm("cvt.rna.tf32.f32 %0, %1;" : "=r"(u) : "f"(f));
    return u;
}
__device__ __forceinline__ float cvt_tf32(float f) {
    return __uint_as_float(f2tf32(f));
}

// ---------------------------------------------------------------------------
// Packed weight layout (per BK=16 tile t):
//   dst = ((t*2 + ks)*32 + j)*64 + lane*2 + r
//   src = W[k][col], k = t*16 + ks*8 + (lane&3) + r*4, col = j*8 + (lane>>2)
// ---------------------------------------------------------------------------

// ---------------------------------------------------------------------------
// Kernel 1: gather + segment mean, TWO warps per node (+ fused weight pack).
// MONOLITHIC: needs the full grid's warp parallelism to saturate DRAM.
// ---------------------------------------------------------------------------
__global__ void gather_mean(const float* __restrict__ E, const float* __restrict__ R,
                            const int* __restrict__ ents,
                            const int* __restrict__ nent,
                            const int* __restrict__ nrel,
                            const int* __restrict__ offs,
                            const float* __restrict__ Wt,
                            const float* __restrict__ Wn,
                            const float* __restrict__ Wr,
                            const float* __restrict__ bt,
                            const float* __restrict__ bn) {
    // ---- fused weight pack (independent of gather work) ----
    {
        const int gt = blockIdx.x * blockDim.x + threadIdx.x;
        const int w1_sz = K1 * H;         // 98304
        const int wr_sz = K2 * H;         // 131072
        if (gt < w1_sz) {
            const int r    = gt & 1;
            const int lane = (gt >> 1) & 31;
            const int j    = (gt >> 6) & 31;
            const int ks   = (gt >> 11) & 1;
            const int t    = gt >> 12;
            const int k    = t * 16 + ks * 8 + (lane & 3) + r * 4;
            const int col  = j * 8 + (lane >> 2);
            const float v  = (k < D) ? Wt[k * H + col] : Wn[(k - D) * H + col];
            g_W1p[gt] = cvt_tf32(v);
        } else if (gt < w1_sz + wr_sz) {
            const int idx  = gt - w1_sz;
            const int r    = idx & 1;
            const int lane = (idx >> 1) & 31;
            const int j    = (idx >> 6) & 31;
            const int ks   = (idx >> 11) & 1;
            const int t    = idx >> 12;
            const int k    = t * 16 + ks * 8 + (lane & 3) + r * 4;
            const int col  = j * 8 + (lane >> 2);
            g_Wrp[idx] = cvt_tf32(Wr[k * H + col]);
        }
        if (gt < H) g_b1[gt] = bt[gt] + bn[gt];
    }

    const int gw   = (blockIdx.x * blockDim.x + threadIdx.x) >> 5;
    const int lane = threadIdx.x & 31;
    const int node = gw >> 1;
    const bool isE = (gw & 1) == 0;
    if (node >= NODES) return;

    const int start = offs[node];
    const int end   = (node + 1 < NODES) ? offs[node + 1] : T_EDG;
    const int cnt   = end - start;
    const float inv = 1.0f / (float)(cnt > 0 ? cnt : 1);

    float* row = g_A1 + (size_t)node * K1;

    if (isE) {
        const float4* E4 = (const float4*)E;
        float4 s = make_float4(0.f, 0.f, 0.f, 0.f);
        if (cnt == 32) {
            const int idx = nent[start + lane];
            #pragma unroll 8
            for (int j = 0; j < 32; j++) {
                const int ie = __shfl_sync(0xffffffffu, idx, j);
                float4 v = __ldg(&E4[(size_t)ie * (D / 4) + lane]);
                s.x += v.x; s.y += v.y; s.z += v.z; s.w += v.w;
            }
        } else {
            for (int base = start; base < end; base += 32) {
                const int rem = end - base;
                const int n   = rem < 32 ? rem : 32;
                const int idx = (lane < rem) ? nent[base + lane] : 0;
                #pragma unroll 4
                for (int j = 0; j < n; j++) {
                    const int ie = __shfl_sync(0xffffffffu, idx, j);
                    float4 v = __ldg(&E4[(size_t)ie * (D / 4) + lane]);
                    s.x += v.x; s.y += v.y; s.z += v.z; s.w += v.w;
                }
            }
        }
        float4 e = __ldg(&E4[(size_t)ents[node] * (D / 4) + lane]);
        float4 o0, o1;
        o0.x = cvt_tf32(e.x);       o0.y = cvt_tf32(e.y);
        o0.z = cvt_tf32(e.z);       o0.w = cvt_tf32(e.w);
        o1.x = cvt_tf32(s.x * inv); o1.y = cvt_tf32(s.y * inv);
        o1.z = cvt_tf32(s.z * inv); o1.w = cvt_tf32(s.w * inv);
        *(float4*)(row + lane * 4)     = o0;
        *(float4*)(row + D + lane * 4) = o1;
    } else {
        const float4* R4 = (const float4*)R;
        float4 s = make_float4(0.f, 0.f, 0.f, 0.f);
        if (cnt == 32) {
            const int idx = nrel[start + lane];
            #pragma unroll 8
            for (int j = 0; j < 32; j++) {
                const int ir = __shfl_sync(0xffffffffu, idx, j);
                float4 v = __ldg(&R4[(size_t)ir * (D / 4) + lane]);
                s.x += v.x; s.y += v.y; s.z += v.z; s.w += v.w;
            }
        } else {
            for (int base = start; base < end; base += 32) {
                const int rem = end - base;
                const int n   = rem < 32 ? rem : 32;
                const int idx = (lane < rem) ? nrel[base + lane] : 0;
                #pragma unroll 4
                for (int j = 0; j < n; j++) {
                    const int ir = __shfl_sync(0xffffffffu, idx, j);
                    float4 v = __ldg(&R4[(size_t)ir * (D / 4) + lane]);
                    s.x += v.x; s.y += v.y; s.z += v.z; s.w += v.w;
                }
            }
        }
        float4 o2;
        o2.x = cvt_tf32(s.x * inv); o2.y = cvt_tf32(s.y * inv);
        o2.z = cvt_tf32(s.z * inv); o2.w = cvt_tf32(s.w * inv);
        *(float4*)(row + 2 * D + lane * 4) = o2;
    }
}

// ---------------------------------------------------------------------------
__device__ __forceinline__ void cp16(void* smem, const void* gmem) {
    uint32_t s = (uint32_t)__cvta_generic_to_shared(smem);
    asm volatile("cp.async.cg.shared.global [%0], [%1], 16;" :: "r"(s), "l"(gmem));
}
__device__ __forceinline__ void mma_tf32(float* a4, uint32_t a0, uint32_t a1,
                                         uint32_t a2, uint32_t a3,
                                         uint32_t b0, uint32_t b1) {
    asm volatile(
        "mma.sync.aligned.m16n8k8.row.col.f32.tf32.tf32.f32 "
        "{%0,%1,%2,%3}, {%4,%5,%6,%7}, {%8,%9}, {%0,%1,%2,%3};"
        : "+f"(a4[0]), "+f"(a4[1]), "+f"(a4[2]), "+f"(a4[3])
        : "r"(a0), "r"(a1), "r"(a2), "r"(a3), "r"(b0), "r"(b1));
}

// ---------------------------------------------------------------------------
// Fused MLP: one CTA per 32 node-rows (= 16 pairs), 256 threads, 256 CTAs.
// 2-stage double buffer -> 70.9 KB smem -> 3 CTAs/SM (24 warps/SM).
// ---------------------------------------------------------------------------
constexpr int BK     = 16;
constexpr int STAGES = 2;
constexpr int BM     = 32;
constexpr int BN     = 256;
constexpr int SAS    = BK + 4;             // 20
constexpr int SN     = 258;                // node-tile stride (conflict-free)
constexpr int A_SZ   = BM * SAS;           // 640
constexpr int B_SZ   = BK * BN;            // 4096 (packed, linear)
constexpr int FUSED_SMEM =
    (BM * SN + STAGES * A_SZ + STAGES * B_SZ) * 4;   // 70912 B

__global__ void __launch_bounds__(256, 3)
fused_mlp(const float* __restrict__ A1full, const float* __restrict__ W1p,
          const float* __restrict__ b1g, const float* __restrict__ Wrp,
          const float* __restrict__ br, float* __restrict__ out) {
    constexpr int THREADS = 256;

    extern __shared__ float smem[];
    float* sN  = smem;                      // [32][SN]
    float* sAb = smem + BM * SN;            // STAGES * A_SZ
    float* sBb = sAb + STAGES * A_SZ;       // STAGES * B_SZ

    const int tid  = threadIdx.x;
    const int wid  = tid >> 5;
    const int lane = tid & 31;
    const int grp  = lane >> 2;
    const int tg   = lane & 3;
    const int by   = blockIdx.x;

    const float* Ag = A1full + (size_t)by * BM * K1;

    auto issueA = [&](int t, int stg) {
        if (tid < 128) {
            float* sA = sAb + stg * A_SZ;
            int row = tid >> 2;
            int c4  = tid & 3;
            cp16(&sA[row * SAS + c4 * 4],
                 Ag + (size_t)row * K1 + t * BK + c4 * 4);
        }
    };
    auto issueB = [&](const float* Wsrc, int t, int stg) {
        float* sB = sBb + stg * B_SZ;
        const float* src = Wsrc + (size_t)t * B_SZ;
        #pragma unroll
        for (int l = 0; l < 4; l++) {       // 4096 floats / (256 thr * 4) = 4
            int o = (tid + l * THREADS) * 4;
            cp16(&sB[o], src + o);
        }
    };

    // =========================== PHASE 1 ===================================
    // warps 2x4: wm = wid&1 (rows), wn = wid>>1 (cols); warp tile 16x64
    {
        const int wm = wid & 1;
        const int wn = wid >> 1;

        float acc[8][4];
        #pragma unroll
        for (int j = 0; j < 8; j++)
            #pragma unroll
            for (int c = 0; c < 4; c++) acc[j][c] = 0.f;

        const int nt1 = K1 / BK;   // 24
        // prologue: tile 0 -> stage 0
        issueA(0, 0); issueB(W1p, 0, 0);
        asm volatile("cp.async.commit_group;");

        const int rb = wm * 16 + grp;
        for (int t = 0; t < nt1; t++) {
            asm volatile("cp.async.wait_group 0;");   // tile t landed
            __syncthreads();
            const int nt = t + 1;
            if (nt < nt1) { issueA(nt, nt & 1); issueB(W1p, nt, nt & 1); }
            asm volatile("cp.async.commit_group;");   // load(t+1) overlaps compute(t)

            const float* sA = sAb + (t & 1) * A_SZ;
            const float* sB = sBb + (t & 1) * B_SZ;
            #pragma unroll
            for (int ks = 0; ks < 2; ks++) {
                uint32_t a0 = __float_as_uint(sA[(rb + 0) * SAS + ks * 8 + tg]);
                uint32_t a1 = __float_as_uint(sA[(rb + 8) * SAS + ks * 8 + tg]);
                uint32_t a2 = __float_as_uint(sA[(rb + 0) * SAS + ks * 8 + tg + 4]);
                uint32_t a3 = __float_as_uint(sA[(rb + 8) * SAS + ks * 8 + tg + 4]);
                #pragma unroll
                for (int jl = 0; jl < 8; jl++) {
                    const int j = wn * 8 + jl;
                    float2 b = *(const float2*)(&sB[((ks * 32 + j) << 6) + lane * 2]);
                    mma_tf32(acc[jl], a0, a1, a2, a3,
                             __float_as_uint(b.x), __float_as_uint(b.y));
                }
            }
        }

        asm volatile("cp.async.wait_group 0;");

        // epilogue 1: bias + relu + tf32 -> sN
        #pragma unroll
        for (int jl = 0; jl < 8; jl++) {
            const int c = wn * 64 + jl * 8 + tg * 2;
            const float b0 = b1g[c], b1v = b1g[c + 1];
            float2 v0, v1;
            v0.x = cvt_tf32(fmaxf(acc[jl][0] + b0, 0.f));
            v0.y = cvt_tf32(fmaxf(acc[jl][1] + b1v, 0.f));
            v1.x = cvt_tf32(fmaxf(acc[jl][2] + b0, 0.f));
            v1.y = cvt_tf32(fmaxf(acc[jl][3] + b1v, 0.f));
            *(float2*)(&sN[(rb + 0) * SN + c]) = v0;
            *(float2*)(&sN[(rb + 8) * SN + c]) = v1;
        }
        __syncthreads();
    }

    // =========================== PHASE 2 ===================================
    // 16 pairs x 256; warps 1x8 (wn2 = wid); warp tile 16x32 (NF=4)
    // A(p,k) = sN[(2p + (k>=256)) * SN + (k&255)]
    {
        const int wn2 = wid;

        float acc[4][4];
        #pragma unroll
        for (int j = 0; j < 4; j++)
            #pragma unroll
            for (int c = 0; c < 4; c++) acc[j][c] = 0.f;

        const int nt2 = K2 / BK;   // 32
        issueB(Wrp, 0, 0);
        asm volatile("cp.async.commit_group;");

        for (int t = 0; t < nt2; t++) {
            asm volatile("cp.async.wait_group 0;");
            __syncthreads();
            const int nt = t + 1;
            if (nt < nt2) issueB(Wrp, nt, nt & 1);
            asm volatile("cp.async.commit_group;");

            const float* sB = sBb + (t & 1) * B_SZ;
            #pragma unroll
            for (int ks = 0; ks < 2; ks++) {
                const int k  = t * BK + ks * 8;
                const int h  = (k >= 256) ? 1 : 0;
                const int kk = k & 255;
                uint32_t a0 = __float_as_uint(sN[(2 * (grp + 0) + h) * SN + kk + tg]);
                uint32_t a1 = __float_as_uint(sN[(2 * (grp + 8) + h) * SN + kk + tg]);
                uint32_t a2 = __float_as_uint(sN[(2 * (grp + 0) + h) * SN + kk + tg + 4]);
                uint32_t a3 = __float_as_uint(sN[(2 * (grp + 8) + h) * SN + kk + tg + 4]);
                #pragma unroll
                for (int jl = 0; jl < 4; jl++) {
                    const int j = wn2 * 4 + jl;
                    float2 b = *(const float2*)(&sB[((ks * 32 + j) << 6) + lane * 2]);
                    mma_tf32(acc[jl], a0, a1, a2, a3,
                             __float_as_uint(b.x), __float_as_uint(b.y));
                }
            }
        }

        // epilogue 2: bias + relu -> gmem
        const int prow = by * 16 + grp;
        #pragma unroll
        for (int jl = 0; jl < 4; jl++) {
            const int c = wn2 * 32 + jl * 8 + tg * 2;
            const float b0 = br[c], b1v = br[c + 1];
            float2 v0, v1;
            v0.x = fmaxf(acc[jl][0] + b0, 0.f);
            v0.y = fmaxf(acc[jl][1] + b1v, 0.f);
            v1.x = fmaxf(acc[jl][2] + b0, 0.f);
            v1.y = fmaxf(acc[jl][3] + b1v, 0.f);
            *(float2*)(out + (size_t)(prow + 0) * H + c) = v0;
            *(float2*)(out + (size_t)(prow + 8) * H + c) = v1;
        }
    }
}

// ---------------------------------------------------------------------------
extern "C" void kernel_launch(void* const* d_in, const int* in_sizes, int n_in,
                              void* d_out, int out_size) {
    const float* E    = (const float*)d_in[0];
    const float* R    = (const float*)d_in[1];
    const float* Wt   = (const float*)d_in[2];
    const float* bt   = (const float*)d_in[3];
    const float* Wn   = (const float*)d_in[4];
    const float* bn   = (const float*)d_in[5];
    const float* Wr   = (const float*)d_in[6];
    const float* br   = (const float*)d_in[7];
    const int*   ents = (const int*)d_in[8];
    const int*   nent = (const int*)d_in[9];
    const int*   nrel = (const int*)d_in[10];
    const int*   offs = (const int*)d_in[11];
    float* out = (float*)d_out;

    float *A1, *W1p, *Wrp, *b1;
    cudaGetSymbolAddress((void**)&A1,  g_A1);
    cudaGetSymbolAddress((void**)&W1p, g_W1p);
    cudaGetSymbolAddress((void**)&Wrp, g_Wrp);
    cudaGetSymbolAddress((void**)&b1,  g_b1);

    cudaFuncSetAttribute(fused_mlp,
                         cudaFuncAttributeMaxDynamicSharedMemorySize, FUSED_SMEM);

    // 1) gather + segment mean (+ fused weight pack), MONOLITHIC
    gather_mean<<<NODES / 4, 256>>>(E, R, ents, nent, nrel, offs,
                                    Wt, Wn, Wr, bt, bn);

    // 2+3) fused node-MLP + pair-MLP: 256 CTAs x 256 threads, 3 CTAs/SM
    fused_mlp<<<NODES / BM, 256, FUSED_SMEM>>>(A1, W1p, b1, Wrp, br, out);
}

// round 12
// speedup vs baseline: 3.9207x; 1.4368x over previous
#include <cuda_runtime.h>
#include <cuda_fp16.h>
#include <cstdint>

// Problem constants (fixed by the dataset)
constexpr int D      = 128;     // embed size
constexpr int H      = 256;     // hidden size
constexpr int NODES  = 8192;    // 2*B
constexpr int BP     = 4096;    // pairs
constexpr int T_EDG  = NODES * 32;
constexpr int K1     = 3 * D;   // 384
constexpr int K2     = 2 * H;   // 512

// Scratch
__device__ __half g_A1[(size_t)NODES * K1];   // fp16 gather output
__device__ __half g_W1p[K1 * H];              // W1 packed in mma-fragment order
__device__ __half g_Wrp[K2 * H];              // Wr packed in mma-fragment order
__device__ float  g_b1[H];

// ---------------------------------------------------------------------------
// Kernel 0: pack weights into m16n8k16 fp16 fragment order + fuse bias.
// Word w (half2): r=w&1 (b0/b1), lane=(w>>1)&31, j=(w>>6)&31, t=w>>11.
//   k  = t*16 + (lane&3)*2 + r*8   (pair k, k+1)
//   col= j*8 + (lane>>2)
// GEMM loads uint2 {b0,b1} at word ((t*32+j)*32+lane)*2 -> LDS.64 conflict-free
// ---------------------------------------------------------------------------
__global__ void prep_w(const float* __restrict__ Wt, const float* __restrict__ Wn,
                       const float* __restrict__ Wr,
                       const float* __restrict__ bt, const float* __restrict__ bn) {
    const int w = blockIdx.x * blockDim.x + threadIdx.x;
    const int W1W = K1 * H / 2;   // 49152 half2 words
    const int WRW = K2 * H / 2;   // 65536
    if (w < W1W) {
        const int r = w & 1, lane = (w >> 1) & 31, j = (w >> 6) & 31, t = w >> 11;
        const int gk  = t * 16 + (lane & 3) * 2 + r * 8;
        const int col = j * 8 + (lane >> 2);
        const float f0 = (gk     < D) ? Wt[gk * H + col]       : Wn[(gk - D) * H + col];
        const float f1 = (gk + 1 < D) ? Wt[(gk + 1) * H + col] : Wn[(gk + 1 - D) * H + col];
        ((half2*)g_W1p)[w] = __floats2half2_rn(f0, f1);
    } else if (w < W1W + WRW) {
        const int idx = w - W1W;
        const int r = idx & 1, lane = (idx >> 1) & 31, j = (idx >> 6) & 31, t = idx >> 11;
        const int gk  = t * 16 + (lane & 3) * 2 + r * 8;
        const int col = j * 8 + (lane >> 2);
        ((half2*)g_Wrp)[idx] =
            __floats2half2_rn(Wr[gk * H + col], Wr[(gk + 1) * H + col]);
    }
    if (w < H) g_b1[w] = bt[w] + bn[w];
}

// ---------------------------------------------------------------------------
// Kernel 1: gather + segment mean, TWO warps per node. MONOLITHIC.
// Output rows written as fp16.
// ---------------------------------------------------------------------------
__global__ void gather_mean(const float* __restrict__ E, const float* __restrict__ R,
                            const int* __restrict__ ents,
                            const int* __restrict__ nent,
                            const int* __restrict__ nrel,
                            const int* __restrict__ offs) {
    const int gw   = (blockIdx.x * blockDim.x + threadIdx.x) >> 5;
    const int lane = threadIdx.x & 31;
    const int node = gw >> 1;
    const bool isE = (gw & 1) == 0;
    if (node >= NODES) return;

    const int start = offs[node];
    const int end   = (node + 1 < NODES) ? offs[node + 1] : T_EDG;
    const int cnt   = end - start;
    const float inv = 1.0f / (float)(cnt > 0 ? cnt : 1);

    __half* row = g_A1 + (size_t)node * K1;

    if (isE) {
        const float4* E4 = (const float4*)E;
        float4 s = make_float4(0.f, 0.f, 0.f, 0.f);
        if (cnt == 32) {
            const int idx = nent[start + lane];
            #pragma unroll 8
            for (int j = 0; j < 32; j++) {
                const int ie = __shfl_sync(0xffffffffu, idx, j);
                float4 v = __ldg(&E4[(size_t)ie * (D / 4) + lane]);
                s.x += v.x; s.y += v.y; s.z += v.z; s.w += v.w;
            }
        } else {
            for (int base = start; base < end; base += 32) {
                const int rem = end - base;
                const int n   = rem < 32 ? rem : 32;
                const int idx = (lane < rem) ? nent[base + lane] : 0;
                #pragma unroll 4
                for (int j = 0; j < n; j++) {
                    const int ie = __shfl_sync(0xffffffffu, idx, j);
                    float4 v = __ldg(&E4[(size_t)ie * (D / 4) + lane]);
                    s.x += v.x; s.y += v.y; s.z += v.z; s.w += v.w;
                }
            }
        }
        float4 e = __ldg(&E4[(size_t)ents[node] * (D / 4) + lane]);
        *(half2*)(row + lane * 4)         = __floats2half2_rn(e.x, e.y);
        *(half2*)(row + lane * 4 + 2)     = __floats2half2_rn(e.z, e.w);
        *(half2*)(row + D + lane * 4)     = __floats2half2_rn(s.x * inv, s.y * inv);
        *(half2*)(row + D + lane * 4 + 2) = __floats2half2_rn(s.z * inv, s.w * inv);
    } else {
        const float4* R4 = (const float4*)R;
        float4 s = make_float4(0.f, 0.f, 0.f, 0.f);
        if (cnt == 32) {
            const int idx = nrel[start + lane];
            #pragma unroll 8
            for (int j = 0; j < 32; j++) {
                const int ir = __shfl_sync(0xffffffffu, idx, j);
                float4 v = __ldg(&R4[(size_t)ir * (D / 4) + lane]);
                s.x += v.x; s.y += v.y; s.z += v.z; s.w += v.w;
            }
        } else {
            for (int base = start; base < end; base += 32) {
                const int rem = end - base;
                const int n   = rem < 32 ? rem : 32;
                const int idx = (lane < rem) ? nrel[base + lane] : 0;
                #pragma unroll 4
                for (int j = 0; j < n; j++) {
                    const int ir = __shfl_sync(0xffffffffu, idx, j);
                    float4 v = __ldg(&R4[(size_t)ir * (D / 4) + lane]);
                    s.x += v.x; s.y += v.y; s.z += v.z; s.w += v.w;
                }
            }
        }
        *(half2*)(row + 2 * D + lane * 4)     = __floats2half2_rn(s.x * inv, s.y * inv);
        *(half2*)(row + 2 * D + lane * 4 + 2) = __floats2half2_rn(s.z * inv, s.w * inv);
    }
}

// ---------------------------------------------------------------------------
__device__ __forceinline__ void cp16(void* smem, const void* gmem) {
    uint32_t s = (uint32_t)__cvta_generic_to_shared(smem);
    asm volatile("cp.async.cg.shared.global [%0], [%1], 16;" :: "r"(s), "l"(gmem));
}
__device__ __forceinline__ void mma_f16(float* a4, uint32_t a0, uint32_t a1,
                                        uint32_t a2, uint32_t a3,
                                        uint32_t b0, uint32_t b1) {
    asm volatile(
        "mma.sync.aligned.m16n8k16.row.col.f32.f16.f16.f32 "
        "{%0,%1,%2,%3}, {%4,%5,%6,%7}, {%8,%9}, {%0,%1,%2,%3};"
        : "+f"(a4[0]), "+f"(a4[1]), "+f"(a4[2]), "+f"(a4[3])
        : "r"(a0), "r"(a1), "r"(a2), "r"(a3), "r"(b0), "r"(b1));
}

// ---------------------------------------------------------------------------
// Fused MLP (fp16 operands): one CTA per 32 node-rows (= 16 pairs), 256 thr.
// Phase 1: nodeTile[32,256] = fp16(relu(A1tile @ W1 + b1)) -> SMEM (sN)
// Phase 2: out[16,256]      = relu(pairview(sN)[16,512] @ Wr + br)
// Strides (halfs): A-tile 40 (word grp-stride 20 -> conflict-free),
//                  sN 260 (word grp-stride 4 mod 32 -> conflict-free).
// ---------------------------------------------------------------------------
constexpr int BKH    = 16;                 // k per tile == k per mma
constexpr int STAGES = 4;
constexpr int BM     = 32;
constexpr int SAS2   = 40;                 // A-tile halfs per row
constexpr int SN2    = 260;                // sN halfs per row
constexpr int A_SZH  = BM * SAS2;          // 1280 halfs / stage
constexpr int B_SZH  = BKH * H;            // 4096 halfs / stage
constexpr int SN_H   = BM * SN2;           // 8320 halfs
constexpr int FUSED_SMEM =
    (SN_H + STAGES * A_SZH + STAGES * B_SZH) * 2;    // 59648 B

__global__ void __launch_bounds__(256, 2)
fused_mlp(const __half* __restrict__ A1full, const __half* __restrict__ W1p,
          const float* __restrict__ b1g, const __half* __restrict__ Wrp,
          const float* __restrict__ br, float* __restrict__ out) {
    constexpr int THREADS = 256;

    extern __shared__ __align__(16) __half smh[];
    __half* sN  = smh;                       // [32][SN2]
    __half* sAb = smh + SN_H;                // STAGES * A_SZH
    __half* sBb = sAb + STAGES * A_SZH;      // STAGES * B_SZH

    const int tid  = threadIdx.x;
    const int wid  = tid >> 5;
    const int lane = tid & 31;
    const int grp  = lane >> 2;
    const int tg   = lane & 3;
    const int by   = blockIdx.x;

    const __half* Ag = A1full + (size_t)by * BM * K1;

    auto issueA = [&](int t, int stg) {
        // 32 rows * 2 chunks(16B=8 halfs) = 64; threads 0..63
        if (tid < 64) {
            __half* sA = sAb + stg * A_SZH;
            int row = tid >> 1;
            int c4  = tid & 1;
            cp16(sA + row * SAS2 + c4 * 8,
                 Ag + (size_t)row * K1 + t * BKH + c4 * 8);
        }
    };
    auto issueB = [&](const __half* Wsrc, int t, int stg) {
        __half* sB = sBb + stg * B_SZH;
        const __half* src = Wsrc + (size_t)t * B_SZH;
        #pragma unroll
        for (int l = 0; l < 2; l++) {        // 4096 halfs / (256 thr * 8) = 2
            int o = (tid + l * THREADS) * 8;
            cp16(sB + o, src + o);
        }
    };

    // =========================== PHASE 1 ===================================
    // warps 2x4: wm = wid&1 (rows), wn = wid>>1 (cols); warp tile 16x64
    {
        const int wm = wid & 1;
        const int wn = wid >> 1;

        float acc[8][4];
        #pragma unroll
        for (int j = 0; j < 8; j++)
            #pragma unroll
            for (int c = 0; c < 4; c++) acc[j][c] = 0.f;

        const int nt1 = K1 / BKH;   // 24
        #pragma unroll
        for (int s = 0; s < STAGES - 1; s++) {
            issueA(s, s); issueB(W1p, s, s);
            asm volatile("cp.async.commit_group;");
        }

        const int rb = wm * 16 + grp;
        for (int t = 0; t < nt1; t++) {
            asm volatile("cp.async.wait_group %0;" :: "n"(STAGES - 2));
            __syncthreads();
            const int nt = t + STAGES - 1;
            if (nt < nt1) { issueA(nt, nt % STAGES); issueB(W1p, nt, nt % STAGES); }
            asm volatile("cp.async.commit_group;");

            const uint32_t* sAw = (const uint32_t*)(sAb + (t % STAGES) * A_SZH);
            const uint2*    sBq = (const uint2*)(sBb + (t % STAGES) * B_SZH);

            const uint32_t a0 = sAw[(rb + 0) * (SAS2 / 2) + tg];
            const uint32_t a1 = sAw[(rb + 8) * (SAS2 / 2) + tg];
            const uint32_t a2 = sAw[(rb + 0) * (SAS2 / 2) + 4 + tg];
            const uint32_t a3 = sAw[(rb + 8) * (SAS2 / 2) + 4 + tg];
            #pragma unroll
            for (int jl = 0; jl < 8; jl++) {
                const int j = wn * 8 + jl;
                uint2 b = sBq[j * 32 + lane];
                mma_f16(acc[jl], a0, a1, a2, a3, b.x, b.y);
            }
        }

        asm volatile("cp.async.wait_group 0;");

        // epilogue 1: bias + relu + fp16 -> sN
        half2* sNh2 = (half2*)sN;
        #pragma unroll
        for (int jl = 0; jl < 8; jl++) {
            const int c = wn * 64 + jl * 8 + tg * 2;
            const float b0 = b1g[c], b1v = b1g[c + 1];
            sNh2[((rb + 0) * SN2 + c) >> 1] =
                __floats2half2_rn(fmaxf(acc[jl][0] + b0, 0.f),
                                  fmaxf(acc[jl][1] + b1v, 0.f));
            sNh2[((rb + 8) * SN2 + c) >> 1] =
                __floats2half2_rn(fmaxf(acc[jl][2] + b0, 0.f),
                                  fmaxf(acc[jl][3] + b1v, 0.f));
        }
        __syncthreads();
    }

    // =========================== PHASE 2 ===================================
    // 16 pairs x 256; warps 1x8 (wn2 = wid); warp tile 16x32 (NF=4)
    // A(p,k) = sN[(2p + (k>=256)) * SN2 + (k&255)]
    {
        const int wn2 = wid;
        const uint32_t* sNw = (const uint32_t*)sN;

        float acc[4][4];
        #pragma unroll
        for (int j = 0; j < 4; j++)
            #pragma unroll
            for (int c = 0; c < 4; c++) acc[j][c] = 0.f;

        const int nt2 = K2 / BKH;   // 32
        #pragma unroll
        for (int s = 0; s < STAGES - 1; s++) {
            issueB(Wrp, s, s);
            asm volatile("cp.async.commit_group;");
        }

        for (int t = 0; t < nt2; t++) {
            asm volatile("cp.async.wait_group %0;" :: "n"(STAGES - 2));
            __syncthreads();
            const int nt = t + STAGES - 1;
            if (nt < nt2) issueB(Wrp, nt, nt % STAGES);
            asm volatile("cp.async.commit_group;");

            const uint2* sBq = (const uint2*)(sBb + (t % STAGES) * B_SZH);
            const int k   = t * BKH;
            const int h   = (k >= 256) ? 1 : 0;
            const int kk2 = (k & 255) >> 1;

            const uint32_t a0 = sNw[(2 * (grp + 0) + h) * (SN2 / 2) + kk2 + tg];
            const uint32_t a1 = sNw[(2 * (grp + 8) + h) * (SN2 / 2) + kk2 + tg];
            const uint32_t a2 = sNw[(2 * (grp + 0) + h) * (SN2 / 2) + kk2 + 4 + tg];
            const uint32_t a3 = sNw[(2 * (grp + 8) + h) * (SN2 / 2) + kk2 + 4 + tg];
            #pragma unroll
            for (int jl = 0; jl < 4; jl++) {
                const int j = wn2 * 4 + jl;
                uint2 b = sBq[j * 32 + lane];
                mma_f16(acc[jl], a0, a1, a2, a3, b.x, b.y);
            }
        }

        // epilogue 2: bias + relu -> gmem (fp32)
        const int prow = by * 16 + grp;
        #pragma unroll
        for (int jl = 0; jl < 4; jl++) {
            const int c = wn2 * 32 + jl * 8 + tg * 2;
            const float b0 = br[c], b1v = br[c + 1];
            float2 v0, v1;
            v0.x = fmaxf(acc[jl][0] + b0, 0.f);
            v0.y = fmaxf(acc[jl][1] + b1v, 0.f);
            v1.x = fmaxf(acc[jl][2] + b0, 0.f);
            v1.y = fmaxf(acc[jl][3] + b1v, 0.f);
            *(float2*)(out + (size_t)(prow + 0) * H + c) = v0;
            *(float2*)(out + (size_t)(prow + 8) * H + c) = v1;
        }
    }
}

// ---------------------------------------------------------------------------
extern "C" void kernel_launch(void* const* d_in, const int* in_sizes, int n_in,
                              void* d_out, int out_size) {
    const float* E    = (const float*)d_in[0];
    const float* R    = (const float*)d_in[1];
    const float* Wt   = (const float*)d_in[2];
    const float* bt   = (const float*)d_in[3];
    const float* Wn   = (const float*)d_in[4];
    const float* bn   = (const float*)d_in[5];
    const float* Wr   = (const float*)d_in[6];
    const float* br   = (const float*)d_in[7];
    const int*   ents = (const int*)d_in[8];
    const int*   nent = (const int*)d_in[9];
    const int*   nrel = (const int*)d_in[10];
    const int*   offs = (const int*)d_in[11];
    float* out = (float*)d_out;

    __half *A1, *W1p, *Wrp;
    float  *b1;
    cudaGetSymbolAddress((void**)&A1,  g_A1);
    cudaGetSymbolAddress((void**)&W1p, g_W1p);
    cudaGetSymbolAddress((void**)&Wrp, g_Wrp);
    cudaGetSymbolAddress((void**)&b1,  g_b1);

    cudaFuncSetAttribute(fused_mlp,
                         cudaFuncAttributeMaxDynamicSharedMemorySize, FUSED_SMEM);

    // 0) fragment-pack weights (fp16) + bias fuse
    prep_w<<<((K1 + K2) * H / 2 + 255) / 256, 256>>>(Wt, Wn, Wr, bt, bn);

    // 1) gather + segment mean, MONOLITHIC (2 warps/node, fp16 output)
    gather_mean<<<NODES / 4, 256>>>(E, R, ents, nent, nrel, offs);

    // 2+3) fused node-MLP + pair-MLP (fp16 mma): 256 CTAs x 256 threads
    fused_mlp<<<NODES / BM, 256, FUSED_SMEM>>>(A1, W1p, b1, Wrp, br, out);
}

// round 13
// speedup vs baseline: 4.2527x; 1.0847x over previous
#include <cuda_runtime.h>
#include <cuda_fp16.h>
#include <cstdint>

// Problem constants (fixed by the dataset)
constexpr int D      = 128;     // embed size
constexpr int H      = 256;     // hidden size
constexpr int NODES  = 8192;    // 2*B
constexpr int BP     = 4096;    // pairs
constexpr int T_EDG  = NODES * 32;
constexpr int K1     = 3 * D;   // 384
constexpr int K2     = 2 * H;   // 512

// Scratch
__device__ __half g_A1[(size_t)NODES * K1];   // fp16 gather output
__device__ __half g_W1p[K1 * H];              // W1 packed in mma-fragment order
__device__ __half g_Wrp[K2 * H];              // Wr packed in mma-fragment order
__device__ float  g_b1[H];

// ---------------------------------------------------------------------------
// Kernel 1: gather + segment mean, TWO warps per node. MONOLITHIC.
// Fused: fp16 m16n8k16 weight-fragment packing + bias fuse (free rider).
// Packed word w (half2): r=w&1, lane=(w>>1)&31, j=(w>>6)&31, t=w>>11.
//   k  = t*16 + (lane&3)*2 + r*8   (pair k, k+1)
//   col= j*8 + (lane>>2)
// ---------------------------------------------------------------------------
__global__ void gather_mean(const float* __restrict__ E, const float* __restrict__ R,
                            const int* __restrict__ ents,
                            const int* __restrict__ nent,
                            const int* __restrict__ nrel,
                            const int* __restrict__ offs,
                            const float* __restrict__ Wt,
                            const float* __restrict__ Wn,
                            const float* __restrict__ Wr,
                            const float* __restrict__ bt,
                            const float* __restrict__ bn) {
    // ---- fused weight pack (independent of gather work) ----
    {
        const int w = blockIdx.x * blockDim.x + threadIdx.x;
        const int W1W = K1 * H / 2;   // 49152 half2 words
        const int WRW = K2 * H / 2;   // 65536
        if (w < W1W) {
            const int r = w & 1, lane = (w >> 1) & 31, j = (w >> 6) & 31, t = w >> 11;
            const int gk  = t * 16 + (lane & 3) * 2 + r * 8;
            const int col = j * 8 + (lane >> 2);
            const float f0 = (gk     < D) ? Wt[gk * H + col]       : Wn[(gk - D) * H + col];
            const float f1 = (gk + 1 < D) ? Wt[(gk + 1) * H + col] : Wn[(gk + 1 - D) * H + col];
            ((half2*)g_W1p)[w] = __floats2half2_rn(f0, f1);
        } else if (w < W1W + WRW) {
            const int idx = w - W1W;
            const int r = idx & 1, lane = (idx >> 1) & 31, j = (idx >> 6) & 31, t = idx >> 11;
            const int gk  = t * 16 + (lane & 3) * 2 + r * 8;
            const int col = j * 8 + (lane >> 2);
            ((half2*)g_Wrp)[idx] =
                __floats2half2_rn(Wr[gk * H + col], Wr[(gk + 1) * H + col]);
        }
        if (w < H) g_b1[w] = bt[w] + bn[w];
    }

    const int gw   = (blockIdx.x * blockDim.x + threadIdx.x) >> 5;
    const int lane = threadIdx.x & 31;
    const int node = gw >> 1;
    const bool isE = (gw & 1) == 0;
    if (node >= NODES) return;

    const int start = offs[node];
    const int end   = (node + 1 < NODES) ? offs[node + 1] : T_EDG;
    const int cnt   = end - start;
    const float inv = 1.0f / (float)(cnt > 0 ? cnt : 1);

    __half* row = g_A1 + (size_t)node * K1;

    if (isE) {
        const float4* E4 = (const float4*)E;
        float4 s = make_float4(0.f, 0.f, 0.f, 0.f);
        if (cnt == 32) {
            const int idx = nent[start + lane];
            #pragma unroll 16
            for (int j = 0; j < 32; j++) {
                const int ie = __shfl_sync(0xffffffffu, idx, j);
                float4 v = __ldg(&E4[(size_t)ie * (D / 4) + lane]);
                s.x += v.x; s.y += v.y; s.z += v.z; s.w += v.w;
            }
        } else {
            for (int base = start; base < end; base += 32) {
                const int rem = end - base;
                const int n   = rem < 32 ? rem : 32;
                const int idx = (lane < rem) ? nent[base + lane] : 0;
                #pragma unroll 4
                for (int j = 0; j < n; j++) {
                    const int ie = __shfl_sync(0xffffffffu, idx, j);
                    float4 v = __ldg(&E4[(size_t)ie * (D / 4) + lane]);
                    s.x += v.x; s.y += v.y; s.z += v.z; s.w += v.w;
                }
            }
        }
        float4 e = __ldg(&E4[(size_t)ents[node] * (D / 4) + lane]);
        *(half2*)(row + lane * 4)         = __floats2half2_rn(e.x, e.y);
        *(half2*)(row + lane * 4 + 2)     = __floats2half2_rn(e.z, e.w);
        *(half2*)(row + D + lane * 4)     = __floats2half2_rn(s.x * inv, s.y * inv);
        *(half2*)(row + D + lane * 4 + 2) = __floats2half2_rn(s.z * inv, s.w * inv);
    } else {
        const float4* R4 = (const float4*)R;
        float4 s = make_float4(0.f, 0.f, 0.f, 0.f);
        if (cnt == 32) {
            const int idx = nrel[start + lane];
            #pragma unroll 16
            for (int j = 0; j < 32; j++) {
                const int ir = __shfl_sync(0xffffffffu, idx, j);
                float4 v = __ldg(&R4[(size_t)ir * (D / 4) + lane]);
                s.x += v.x; s.y += v.y; s.z += v.z; s.w += v.w;
            }
        } else {
            for (int base = start; base < end; base += 32) {
                const int rem = end - base;
                const int n   = rem < 32 ? rem : 32;
                const int idx = (lane < rem) ? nrel[base + lane] : 0;
                #pragma unroll 4
                for (int j = 0; j < n; j++) {
                    const int ir = __shfl_sync(0xffffffffu, idx, j);
                    float4 v = __ldg(&R4[(size_t)ir * (D / 4) + lane]);
                    s.x += v.x; s.y += v.y; s.z += v.z; s.w += v.w;
                }
            }
        }
        *(half2*)(row + 2 * D + lane * 4)     = __floats2half2_rn(s.x * inv, s.y * inv);
        *(half2*)(row + 2 * D + lane * 4 + 2) = __floats2half2_rn(s.z * inv, s.w * inv);
    }
}

// ---------------------------------------------------------------------------
__device__ __forceinline__ void cp16(void* smem, const void* gmem) {
    uint32_t s = (uint32_t)__cvta_generic_to_shared(smem);
    asm volatile("cp.async.cg.shared.global [%0], [%1], 16;" :: "r"(s), "l"(gmem));
}
__device__ __forceinline__ void mma_f16(float* a4, uint32_t a0, uint32_t a1,
                                        uint32_t a2, uint32_t a3,
                                        uint32_t b0, uint32_t b1) {
    asm volatile(
        "mma.sync.aligned.m16n8k16.row.col.f32.f16.f16.f32 "
        "{%0,%1,%2,%3}, {%4,%5,%6,%7}, {%8,%9}, {%0,%1,%2,%3};"
        : "+f"(a4[0]), "+f"(a4[1]), "+f"(a4[2]), "+f"(a4[3])
        : "r"(a0), "r"(a1), "r"(a2), "r"(a3), "r"(b0), "r"(b1));
}

// ---------------------------------------------------------------------------
// Fused MLP (fp16 operands): one CTA per 32 node-rows (= 16 pairs), 256 thr.
// Phase 1: nodeTile[32,256] = fp16(relu(A1tile @ W1 + b1)) -> SMEM (sN)
// Phase 2: out[16,256]      = relu(pairview(sN)[16,512] @ Wr + br)
// ---------------------------------------------------------------------------
constexpr int BKH    = 16;
constexpr int STAGES = 4;
constexpr int BM     = 32;
constexpr int SAS2   = 40;                 // A-tile halfs per row
constexpr int SN2    = 260;                // sN halfs per row
constexpr int A_SZH  = BM * SAS2;          // 1280 halfs / stage
constexpr int B_SZH  = BKH * H;            // 4096 halfs / stage
constexpr int SN_H   = BM * SN2;           // 8320 halfs
constexpr int FUSED_SMEM =
    (SN_H + STAGES * A_SZH + STAGES * B_SZH) * 2;    // 59648 B

__global__ void __launch_bounds__(256, 2)
fused_mlp(const __half* __restrict__ A1full, const __half* __restrict__ W1p,
          const float* __restrict__ b1g, const __half* __restrict__ Wrp,
          const float* __restrict__ br, float* __restrict__ out) {
    constexpr int THREADS = 256;

    extern __shared__ __align__(16) __half smh[];
    __half* sN  = smh;                       // [32][SN2]
    __half* sAb = smh + SN_H;                // STAGES * A_SZH
    __half* sBb = sAb + STAGES * A_SZH;      // STAGES * B_SZH

    const int tid  = threadIdx.x;
    const int wid  = tid >> 5;
    const int lane = tid & 31;
    const int grp  = lane >> 2;
    const int tg   = lane & 3;
    const int by   = blockIdx.x;

    const __half* Ag = A1full + (size_t)by * BM * K1;

    auto issueA = [&](int t, int stg) {
        if (tid < 64) {
            __half* sA = sAb + stg * A_SZH;
            int row = tid >> 1;
            int c4  = tid & 1;
            cp16(sA + row * SAS2 + c4 * 8,
                 Ag + (size_t)row * K1 + t * BKH + c4 * 8);
        }
    };
    auto issueB = [&](const __half* Wsrc, int t, int stg) {
        __half* sB = sBb + stg * B_SZH;
        const __half* src = Wsrc + (size_t)t * B_SZH;
        #pragma unroll
        for (int l = 0; l < 2; l++) {
            int o = (tid + l * THREADS) * 8;
            cp16(sB + o, src + o);
        }
    };

    // =========================== PHASE 1 ===================================
    {
        const int wm = wid & 1;
        const int wn = wid >> 1;

        float acc[8][4];
        #pragma unroll
        for (int j = 0; j < 8; j++)
            #pragma unroll
            for (int c = 0; c < 4; c++) acc[j][c] = 0.f;

        const int nt1 = K1 / BKH;   // 24
        #pragma unroll
        for (int s = 0; s < STAGES - 1; s++) {
            issueA(s, s); issueB(W1p, s, s);
            asm volatile("cp.async.commit_group;");
        }

        const int rb = wm * 16 + grp;
        for (int t = 0; t < nt1; t++) {
            asm volatile("cp.async.wait_group %0;" :: "n"(STAGES - 2));
            __syncthreads();
            const int nt = t + STAGES - 1;
            if (nt < nt1) { issueA(nt, nt % STAGES); issueB(W1p, nt, nt % STAGES); }
            asm volatile("cp.async.commit_group;");

            const uint32_t* sAw = (const uint32_t*)(sAb + (t % STAGES) * A_SZH);
            const uint2*    sBq = (const uint2*)(sBb + (t % STAGES) * B_SZH);

            const uint32_t a0 = sAw[(rb + 0) * (SAS2 / 2) + tg];
            const uint32_t a1 = sAw[(rb + 8) * (SAS2 / 2) + tg];
            const uint32_t a2 = sAw[(rb + 0) * (SAS2 / 2) + 4 + tg];
            const uint32_t a3 = sAw[(rb + 8) * (SAS2 / 2) + 4 + tg];
            #pragma unroll
            for (int jl = 0; jl < 8; jl++) {
                const int j = wn * 8 + jl;
                uint2 b = sBq[j * 32 + lane];
                mma_f16(acc[jl], a0, a1, a2, a3, b.x, b.y);
            }
        }

        asm volatile("cp.async.wait_group 0;");

        // epilogue 1: bias + relu + fp16 -> sN
        half2* sNh2 = (half2*)sN;
        #pragma unroll
        for (int jl = 0; jl < 8; jl++) {
            const int c = wn * 64 + jl * 8 + tg * 2;
            const float b0 = b1g[c], b1v = b1g[c + 1];
            sNh2[((rb + 0) * SN2 + c) >> 1] =
                __floats2half2_rn(fmaxf(acc[jl][0] + b0, 0.f),
                                  fmaxf(acc[jl][1] + b1v, 0.f));
            sNh2[((rb + 8) * SN2 + c) >> 1] =
                __floats2half2_rn(fmaxf(acc[jl][2] + b0, 0.f),
                                  fmaxf(acc[jl][3] + b1v, 0.f));
        }
        __syncthreads();
    }

    // =========================== PHASE 2 ===================================
    {
        const int wn2 = wid;
        const uint32_t* sNw = (const uint32_t*)sN;

        float acc[4][4];
        #pragma unroll
        for (int j = 0; j < 4; j++)
            #pragma unroll
            for (int c = 0; c < 4; c++) acc[j][c] = 0.f;

        const int nt2 = K2 / BKH;   // 32
        #pragma unroll
        for (int s = 0; s < STAGES - 1; s++) {
            issueB(Wrp, s, s);
            asm volatile("cp.async.commit_group;");
        }

        for (int t = 0; t < nt2; t++) {
            asm volatile("cp.async.wait_group %0;" :: "n"(STAGES - 2));
            __syncthreads();
            const int nt = t + STAGES - 1;
            if (nt < nt2) issueB(Wrp, nt, nt % STAGES);
            asm volatile("cp.async.commit_group;");

            const uint2* sBq = (const uint2*)(sBb + (t % STAGES) * B_SZH);
            const int k   = t * BKH;
            const int h   = (k >= 256) ? 1 : 0;
            const int kk2 = (k & 255) >> 1;

            const uint32_t a0 = sNw[(2 * (grp + 0) + h) * (SN2 / 2) + kk2 + tg];
            const uint32_t a1 = sNw[(2 * (grp + 8) + h) * (SN2 / 2) + kk2 + tg];
            const uint32_t a2 = sNw[(2 * (grp + 0) + h) * (SN2 / 2) + kk2 + 4 + tg];
            const uint32_t a3 = sNw[(2 * (grp + 8) + h) * (SN2 / 2) + kk2 + 4 + tg];
            #pragma unroll
            for (int jl = 0; jl < 4; jl++) {
                const int j = wn2 * 4 + jl;
                uint2 b = sBq[j * 32 + lane];
                mma_f16(acc[jl], a0, a1, a2, a3, b.x, b.y);
            }
        }

        // epilogue 2: bias + relu -> gmem (fp32)
        const int prow = by * 16 + grp;
        #pragma unroll
        for (int jl = 0; jl < 4; jl++) {
            const int c = wn2 * 32 + jl * 8 + tg * 2;
            const float b0 = br[c], b1v = br[c + 1];
            float2 v0, v1;
            v0.x = fmaxf(acc[jl][0] + b0, 0.f);
            v0.y = fmaxf(acc[jl][1] + b1v, 0.f);
            v1.x = fmaxf(acc[jl][2] + b0, 0.f);
            v1.y = fmaxf(acc[jl][3] + b1v, 0.f);
            *(float2*)(out + (size_t)(prow + 0) * H + c) = v0;
            *(float2*)(out + (size_t)(prow + 8) * H + c) = v1;
        }
    }
}

// ---------------------------------------------------------------------------
extern "C" void kernel_launch(void* const* d_in, const int* in_sizes, int n_in,
                              void* d_out, int out_size) {
    const float* E    = (const float*)d_in[0];
    const float* R    = (const float*)d_in[1];
    const float* Wt   = (const float*)d_in[2];
    const float* bt   = (const float*)d_in[3];
    const float* Wn   = (const float*)d_in[4];
    const float* bn   = (const float*)d_in[5];
    const float* Wr   = (const float*)d_in[6];
    const float* br   = (const float*)d_in[7];
    const int*   ents = (const int*)d_in[8];
    const int*   nent = (const int*)d_in[9];
    const int*   nrel = (const int*)d_in[10];
    const int*   offs = (const int*)d_in[11];
    float* out = (float*)d_out;

    __half *A1, *W1p, *Wrp;
    float  *b1;
    cudaGetSymbolAddress((void**)&A1,  g_A1);
    cudaGetSymbolAddress((void**)&W1p, g_W1p);
    cudaGetSymbolAddress((void**)&Wrp, g_Wrp);
    cudaGetSymbolAddress((void**)&b1,  g_b1);

    cudaFuncSetAttribute(fused_mlp,
                         cudaFuncAttributeMaxDynamicSharedMemorySize, FUSED_SMEM);

    // 1) gather + segment mean (+ fused fp16 weight pack), MONOLITHIC
    gather_mean<<<NODES / 4, 256>>>(E, R, ents, nent, nrel, offs,
                                    Wt, Wn, Wr, bt, bn);

    // 2+3) fused node-MLP + pair-MLP (fp16 mma): 256 CTAs x 256 threads
    fused_mlp<<<NODES / BM, 256, FUSED_SMEM>>>(A1, W1p, b1, Wrp, br, out);
}

// round 14
// speedup vs baseline: 4.4221x; 1.0398x over previous
#include <cuda_runtime.h>
#include <cuda_fp16.h>
#include <cstdint>

// Problem constants (fixed by the dataset)
constexpr int D      = 128;     // embed size
constexpr int H      = 256;     // hidden size
constexpr int NODES  = 8192;    // 2*B
constexpr int BP     = 4096;    // pairs
constexpr int T_EDG  = NODES * 32;
constexpr int K1     = 3 * D;   // 384
constexpr int K2     = 2 * H;   // 512

// Scratch
__device__ __half g_A1[(size_t)NODES * K1];   // fp16 gather output
__device__ __half g_W1p[K1 * H];              // W1 packed in mma-fragment order
__device__ __half g_Wrp[K2 * H];              // Wr packed in mma-fragment order
__device__ float  g_b1[H];

// ---------------------------------------------------------------------------
// Kernel 1: gather + segment mean, TWO warps per node. MONOLITHIC.
// Fused: fp16 m16n8k16 weight-fragment packing + bias fuse (free rider).
// Packed word w (half2): r=w&1, lane=(w>>1)&31, j=(w>>6)&31, t=w>>11.
//   k  = t*16 + (lane&3)*2 + r*8   (pair k, k+1)
//   col= j*8 + (lane>>2)
// ---------------------------------------------------------------------------
__global__ void gather_mean(const float* __restrict__ E, const float* __restrict__ R,
                            const int* __restrict__ ents,
                            const int* __restrict__ nent,
                            const int* __restrict__ nrel,
                            const int* __restrict__ offs,
                            const float* __restrict__ Wt,
                            const float* __restrict__ Wn,
                            const float* __restrict__ Wr,
                            const float* __restrict__ bt,
                            const float* __restrict__ bn) {
    // ---- fused weight pack (independent of gather work) ----
    {
        const int w = blockIdx.x * blockDim.x + threadIdx.x;
        const int W1W = K1 * H / 2;   // 49152 half2 words
        const int WRW = K2 * H / 2;   // 65536
        if (w < W1W) {
            const int r = w & 1, lane = (w >> 1) & 31, j = (w >> 6) & 31, t = w >> 11;
            const int gk  = t * 16 + (lane & 3) * 2 + r * 8;
            const int col = j * 8 + (lane >> 2);
            const float f0 = (gk     < D) ? Wt[gk * H + col]       : Wn[(gk - D) * H + col];
            const float f1 = (gk + 1 < D) ? Wt[(gk + 1) * H + col] : Wn[(gk + 1 - D) * H + col];
            ((half2*)g_W1p)[w] = __floats2half2_rn(f0, f1);
        } else if (w < W1W + WRW) {
            const int idx = w - W1W;
            const int r = idx & 1, lane = (idx >> 1) & 31, j = (idx >> 6) & 31, t = idx >> 11;
            const int gk  = t * 16 + (lane & 3) * 2 + r * 8;
            const int col = j * 8 + (lane >> 2);
            ((half2*)g_Wrp)[idx] =
                __floats2half2_rn(Wr[gk * H + col], Wr[(gk + 1) * H + col]);
        }
        if (w < H) g_b1[w] = bt[w] + bn[w];
    }

    const int gw   = (blockIdx.x * blockDim.x + threadIdx.x) >> 5;
    const int lane = threadIdx.x & 31;
    const int node = gw >> 1;
    const bool isE = (gw & 1) == 0;
    if (node >= NODES) return;

    const int start = offs[node];
    const int end   = (node + 1 < NODES) ? offs[node + 1] : T_EDG;
    const int cnt   = end - start;
    const float inv = 1.0f / (float)(cnt > 0 ? cnt : 1);

    __half* row = g_A1 + (size_t)node * K1;

    if (isE) {
        const float4* E4 = (const float4*)E;
        float4 s = make_float4(0.f, 0.f, 0.f, 0.f);
        if (cnt == 32) {
            const int idx = nent[start + lane];
            #pragma unroll 16
            for (int j = 0; j < 32; j++) {
                const int ie = __shfl_sync(0xffffffffu, idx, j);
                float4 v = __ldg(&E4[(size_t)ie * (D / 4) + lane]);
                s.x += v.x; s.y += v.y; s.z += v.z; s.w += v.w;
            }
        } else {
            for (int base = start; base < end; base += 32) {
                const int rem = end - base;
                const int n   = rem < 32 ? rem : 32;
                const int idx = (lane < rem) ? nent[base + lane] : 0;
                #pragma unroll 4
                for (int j = 0; j < n; j++) {
                    const int ie = __shfl_sync(0xffffffffu, idx, j);
                    float4 v = __ldg(&E4[(size_t)ie * (D / 4) + lane]);
                    s.x += v.x; s.y += v.y; s.z += v.z; s.w += v.w;
                }
            }
        }
        float4 e = __ldg(&E4[(size_t)ents[node] * (D / 4) + lane]);
        *(half2*)(row + lane * 4)         = __floats2half2_rn(e.x, e.y);
        *(half2*)(row + lane * 4 + 2)     = __floats2half2_rn(e.z, e.w);
        *(half2*)(row + D + lane * 4)     = __floats2half2_rn(s.x * inv, s.y * inv);
        *(half2*)(row + D + lane * 4 + 2) = __floats2half2_rn(s.z * inv, s.w * inv);
    } else {
        const float4* R4 = (const float4*)R;
        float4 s = make_float4(0.f, 0.f, 0.f, 0.f);
        if (cnt == 32) {
            const int idx = nrel[start + lane];
            #pragma unroll 16
            for (int j = 0; j < 32; j++) {
                const int ir = __shfl_sync(0xffffffffu, idx, j);
                float4 v = __ldg(&R4[(size_t)ir * (D / 4) + lane]);
                s.x += v.x; s.y += v.y; s.z += v.z; s.w += v.w;
            }
        } else {
            for (int base = start; base < end; base += 32) {
                const int rem = end - base;
                const int n   = rem < 32 ? rem : 32;
                const int idx = (lane < rem) ? nrel[base + lane] : 0;
                #pragma unroll 4
                for (int j = 0; j < n; j++) {
                    const int ir = __shfl_sync(0xffffffffu, idx, j);
                    float4 v = __ldg(&R4[(size_t)ir * (D / 4) + lane]);
                    s.x += v.x; s.y += v.y; s.z += v.z; s.w += v.w;
                }
            }
        }
        *(half2*)(row + 2 * D + lane * 4)     = __floats2half2_rn(s.x * inv, s.y * inv);
        *(half2*)(row + 2 * D + lane * 4 + 2) = __floats2half2_rn(s.z * inv, s.w * inv);
    }
}

// ---------------------------------------------------------------------------
__device__ __forceinline__ void cp16(void* smem, const void* gmem) {
    uint32_t s = (uint32_t)__cvta_generic_to_shared(smem);
    asm volatile("cp.async.cg.shared.global [%0], [%1], 16;" :: "r"(s), "l"(gmem));
}
__device__ __forceinline__ void mma_f16(float* a4, uint32_t a0, uint32_t a1,
                                        uint32_t a2, uint32_t a3,
                                        uint32_t b0, uint32_t b1) {
    asm volatile(
        "mma.sync.aligned.m16n8k16.row.col.f32.f16.f16.f32 "
        "{%0,%1,%2,%3}, {%4,%5,%6,%7}, {%8,%9}, {%0,%1,%2,%3};"
        : "+f"(a4[0]), "+f"(a4[1]), "+f"(a4[2]), "+f"(a4[3])
        : "r"(a0), "r"(a1), "r"(a2), "r"(a3), "r"(b0), "r"(b1));
}

// ---------------------------------------------------------------------------
// Fused MLP (fp16, BK=32): one CTA per 32 node-rows (= 16 pairs), 256 thr.
// Phase 1 (12 iters): nodeTile[32,256] = fp16(relu(A1tile @ W1 + b1)) -> sN
// Phase 2 (16 iters): out[16,256]      = relu(pairview(sN)[16,512] @ Wr + br)
// Each BK=32 tile = two consecutive packed k16 fragment tiles (layout reused).
// ---------------------------------------------------------------------------
constexpr int BKH    = 32;                 // k per pipeline tile (2 x k16 mma)
constexpr int STAGES = 3;
constexpr int BM     = 32;
constexpr int SAS2   = 40;                 // A-tile halfs/row (32 data + 8 pad)
constexpr int SN2    = 260;                // sN halfs per row
constexpr int A_SZH  = BM * SAS2;          // 1280 halfs / stage
constexpr int B_SZH  = BKH * H;            // 8192 halfs / stage
constexpr int SN_H   = BM * SN2;           // 8320 halfs
constexpr int FUSED_SMEM =
    (SN_H + STAGES * A_SZH + STAGES * B_SZH) * 2;    // 73472 B

__global__ void __launch_bounds__(256, 2)
fused_mlp(const __half* __restrict__ A1full, const __half* __restrict__ W1p,
          const float* __restrict__ b1g, const __half* __restrict__ Wrp,
          const float* __restrict__ br, float* __restrict__ out) {
    constexpr int THREADS = 256;

    extern __shared__ __align__(16) __half smh[];
    __half* sN  = smh;                       // [32][SN2]
    __half* sAb = smh + SN_H;                // STAGES * A_SZH
    __half* sBb = sAb + STAGES * A_SZH;      // STAGES * B_SZH

    const int tid  = threadIdx.x;
    const int wid  = tid >> 5;
    const int lane = tid & 31;
    const int grp  = lane >> 2;
    const int tg   = lane & 3;
    const int by   = blockIdx.x;

    const __half* Ag = A1full + (size_t)by * BM * K1;

    auto issueA = [&](int t, int stg) {
        // 32 rows * 4 chunks(16B = 8 halfs) = 128; threads 0..127
        if (tid < 128) {
            __half* sA = sAb + stg * A_SZH;
            int row = tid >> 2;
            int c4  = tid & 3;
            cp16(sA + row * SAS2 + c4 * 8,
                 Ag + (size_t)row * K1 + t * BKH + c4 * 8);
        }
    };
    auto issueB = [&](const __half* Wsrc, int t, int stg) {
        __half* sB = sBb + stg * B_SZH;
        const __half* src = Wsrc + (size_t)t * B_SZH;
        #pragma unroll
        for (int l = 0; l < 4; l++) {        // 8192 halfs / (256 thr * 8) = 4
            int o = (tid + l * THREADS) * 8;
            cp16(sB + o, src + o);
        }
    };

    // =========================== PHASE 1 ===================================
    // warps 2x4: wm = wid&1 (rows), wn = wid>>1 (cols); warp tile 16x64
    {
        const int wm = wid & 1;
        const int wn = wid >> 1;

        float acc[8][4];
        #pragma unroll
        for (int j = 0; j < 8; j++)
            #pragma unroll
            for (int c = 0; c < 4; c++) acc[j][c] = 0.f;

        const int nt1 = K1 / BKH;   // 12
        #pragma unroll
        for (int s = 0; s < STAGES - 1; s++) {
            issueA(s, s); issueB(W1p, s, s);
            asm volatile("cp.async.commit_group;");
        }

        const int rb = wm * 16 + grp;
        for (int t = 0; t < nt1; t++) {
            asm volatile("cp.async.wait_group %0;" :: "n"(STAGES - 2));
            __syncthreads();
            const int nt = t + STAGES - 1;
            if (nt < nt1) { issueA(nt, nt % STAGES); issueB(W1p, nt, nt % STAGES); }
            asm volatile("cp.async.commit_group;");

            const uint32_t* sAw = (const uint32_t*)(sAb + (t % STAGES) * A_SZH);
            const uint2*    sBq = (const uint2*)(sBb + (t % STAGES) * B_SZH);

            #pragma unroll
            for (int ks = 0; ks < 2; ks++) {
                const uint32_t a0 = sAw[(rb + 0) * (SAS2 / 2) + ks * 8 + tg];
                const uint32_t a1 = sAw[(rb + 8) * (SAS2 / 2) + ks * 8 + tg];
                const uint32_t a2 = sAw[(rb + 0) * (SAS2 / 2) + ks * 8 + 4 + tg];
                const uint32_t a3 = sAw[(rb + 8) * (SAS2 / 2) + ks * 8 + 4 + tg];
                #pragma unroll
                for (int jl = 0; jl < 8; jl++) {
                    const int j = wn * 8 + jl;
                    uint2 b = sBq[ks * 1024 + j * 32 + lane];
                    mma_f16(acc[jl], a0, a1, a2, a3, b.x, b.y);
                }
            }
        }

        asm volatile("cp.async.wait_group 0;");

        // epilogue 1: bias + relu + fp16 -> sN
        half2* sNh2 = (half2*)sN;
        #pragma unroll
        for (int jl = 0; jl < 8; jl++) {
            const int c = wn * 64 + jl * 8 + tg * 2;
            const float b0 = b1g[c], b1v = b1g[c + 1];
            sNh2[((rb + 0) * SN2 + c) >> 1] =
                __floats2half2_rn(fmaxf(acc[jl][0] + b0, 0.f),
                                  fmaxf(acc[jl][1] + b1v, 0.f));
            sNh2[((rb + 8) * SN2 + c) >> 1] =
                __floats2half2_rn(fmaxf(acc[jl][2] + b0, 0.f),
                                  fmaxf(acc[jl][3] + b1v, 0.f));
        }
        __syncthreads();
    }

    // =========================== PHASE 2 ===================================
    // 16 pairs x 256; warps 1x8 (wn2 = wid); warp tile 16x32 (NF=4)
    // A(p,k) = sN[(2p + (k>=256)) * SN2 + (k&255)]
    {
        const int wn2 = wid;
        const uint32_t* sNw = (const uint32_t*)sN;

        float acc[4][4];
        #pragma unroll
        for (int j = 0; j < 4; j++)
            #pragma unroll
            for (int c = 0; c < 4; c++) acc[j][c] = 0.f;

        const int nt2 = K2 / BKH;   // 16
        #pragma unroll
        for (int s = 0; s < STAGES - 1; s++) {
            issueB(Wrp, s, s);
            asm volatile("cp.async.commit_group;");
        }

        for (int t = 0; t < nt2; t++) {
            asm volatile("cp.async.wait_group %0;" :: "n"(STAGES - 2));
            __syncthreads();
            const int nt = t + STAGES - 1;
            if (nt < nt2) issueB(Wrp, nt, nt % STAGES);
            asm volatile("cp.async.commit_group;");

            const uint2* sBq = (const uint2*)(sBb + (t % STAGES) * B_SZH);

            #pragma unroll
            for (int ks = 0; ks < 2; ks++) {
                const int k   = t * BKH + ks * 16;
                const int h   = (k >= 256) ? 1 : 0;
                const int kk2 = (k & 255) >> 1;

                const uint32_t a0 = sNw[(2 * (grp + 0) + h) * (SN2 / 2) + kk2 + tg];
                const uint32_t a1 = sNw[(2 * (grp + 8) + h) * (SN2 / 2) + kk2 + tg];
                const uint32_t a2 = sNw[(2 * (grp + 0) + h) * (SN2 / 2) + kk2 + 4 + tg];
                const uint32_t a3 = sNw[(2 * (grp + 8) + h) * (SN2 / 2) + kk2 + 4 + tg];
                #pragma unroll
                for (int jl = 0; jl < 4; jl++) {
                    const int j = wn2 * 4 + jl;
                    uint2 b = sBq[ks * 1024 + j * 32 + lane];
                    mma_f16(acc[jl], a0, a1, a2, a3, b.x, b.y);
                }
            }
        }

        // epilogue 2: bias + relu -> gmem (fp32)
        const int prow = by * 16 + grp;
        #pragma unroll
        for (int jl = 0; jl < 4; jl++) {
            const int c = wn2 * 32 + jl * 8 + tg * 2;
            const float b0 = br[c], b1v = br[c + 1];
            float2 v0, v1;
            v0.x = fmaxf(acc[jl][0] + b0, 0.f);
            v0.y = fmaxf(acc[jl][1] + b1v, 0.f);
            v1.x = fmaxf(acc[jl][2] + b0, 0.f);
            v1.y = fmaxf(acc[jl][3] + b1v, 0.f);
            *(float2*)(out + (size_t)(prow + 0) * H + c) = v0;
            *(float2*)(out + (size_t)(prow + 8) * H + c) = v1;
        }
    }
}

// ---------------------------------------------------------------------------
extern "C" void kernel_launch(void* const* d_in, const int* in_sizes, int n_in,
                              void* d_out, int out_size) {
    const float* E    = (const float*)d_in[0];
    const float* R    = (const float*)d_in[1];
    const float* Wt   = (const float*)d_in[2];
    const float* bt   = (const float*)d_in[3];
    const float* Wn   = (const float*)d_in[4];
    const float* bn   = (const float*)d_in[5];
    const float* Wr   = (const float*)d_in[6];
    const float* br   = (const float*)d_in[7];
    const int*   ents = (const int*)d_in[8];
    const int*   nent = (const int*)d_in[9];
    const int*   nrel = (const int*)d_in[10];
    const int*   offs = (const int*)d_in[11];
    float* out = (float*)d_out;

    __half *A1, *W1p, *Wrp;
    float  *b1;
    cudaGetSymbolAddress((void**)&A1,  g_A1);
    cudaGetSymbolAddress((void**)&W1p, g_W1p);
    cudaGetSymbolAddress((void**)&Wrp, g_Wrp);
    cudaGetSymbolAddress((void**)&b1,  g_b1);

    cudaFuncSetAttribute(fused_mlp,
                         cudaFuncAttributeMaxDynamicSharedMemorySize, FUSED_SMEM);

    // 1) gather + segment mean (+ fused fp16 weight pack), MONOLITHIC
    gather_mean<<<NODES / 4, 256>>>(E, R, ents, nent, nrel, offs,
                                    Wt, Wn, Wr, bt, bn);

    // 2+3) fused node-MLP + pair-MLP (fp16 mma, BK=32): 256 CTAs x 256 thr
    fused_mlp<<<NODES / BM, 256, FUSED_SMEM>>>(A1, W1p, b1, Wrp, br, out);
}